// round 13
// baseline (speedup 1.0000x reference)
#include <cuda_runtime.h>
#include <cuda_fp16.h>

// Problem constants (fixed by the dataset)
constexpr int NMAX   = 150000;
constexpr int HD     = 32;   // hidden dim
constexpr int STRIDE = 64;   // bucket capacity per node (P(deg>64) ~ 1e-14)

// ---------------- scratch (device globals; zero-init at load) ---------------
// Self-restoring: g_cnt reset by pool kernel, g_pool/g_done by its last block.
__device__ __half g_hA[(long long)NMAX * HD];    // ping features (h*dinv, fp16)
__device__ __half g_hB[(long long)NMAX * HD];    // pong features
__device__ int    g_cnt[NMAX];                   // bucket fill counts == degree
__device__ int    g_csrc[(long long)NMAX * STRIDE]; // bucketed src ids
__device__ float  g_pool[HD];                    // sum-pool result
__device__ int    g_done;                        // pool completion ticket

// ---------------- f32x2 packed math helpers ---------------------------------
__device__ __forceinline__ unsigned long long pack2(float x, float y) {
    unsigned long long r;
    asm("mov.b64 %0, {%1, %2};" : "=l"(r) : "f"(x), "f"(y));
    return r;
}
__device__ __forceinline__ void unpack2(unsigned long long v, float& x, float& y) {
    asm("mov.b64 {%0, %1}, %2;" : "=f"(x), "=f"(y) : "l"(v));
}
__device__ __forceinline__ unsigned long long fma2_(unsigned long long a,
                                                    unsigned long long b,
                                                    unsigned long long c) {
    unsigned long long d;
    asm("fma.rn.f32x2 %0, %1, %2, %3;" : "=l"(d) : "l"(a), "l"(b), "l"(c));
    return d;
}

// ---------------- bucket scatter (2 edges per thread) ------------------------
// edge_index is int32: ei[0:E]=src, ei[E:2E]=dst
__global__ void scatter_kernel(const int* __restrict__ ei, int E, int n) {
    int t = blockIdx.x * blockDim.x + threadIdx.x;
#pragma unroll
    for (int j = 0; j < 2; j++) {
        int e = t * 2 + j;
        if (e >= E) return;
        unsigned s = (unsigned)ei[e];
        unsigned d = (unsigned)ei[E + e];
        if (s < (unsigned)n && d < (unsigned)n) {
            int pos = atomicAdd(&g_cnt[d], 1);
            if (pos < STRIDE) g_csrc[(long long)d * STRIDE + pos] = (int)s;
        }
    }
}

// ---------------- layer 1: g_hA = (x @ W1) * dinv, fp16 out -----------------
// FOUR nodes per warp: g = lane>>3, fl = lane&7; lane owns 4 outputs (2 f32x2).
__global__ void gemm1_kernel(const float* __restrict__ x,
                             const float* __restrict__ W, int n) {
    __shared__ ulonglong2 Wq[61 * 8];   // Wq[k*8+q] = W[k][4q..4q+3] as 2xf32x2
    for (int i = threadIdx.x; i < 61 * 8; i += blockDim.x) {
        float4 f = ((const float4*)W)[i];
        ulonglong2 u;
        u.x = pack2(f.x, f.y);
        u.y = pack2(f.z, f.w);
        Wq[i] = u;
    }
    __syncthreads();
    int warp = (blockIdx.x * blockDim.x + threadIdx.x) >> 5;
    int lane = threadIdx.x & 31;
    int g    = lane >> 3;
    int fl   = lane & 7;
    int node = warp * 4 + g;
    if (warp * 4 >= n) return;
    bool valid = node < n;
    int nd = valid ? node : n - 1;
    const float* xr = x + (long long)nd * 61;
    float xa[8];
#pragma unroll
    for (int j = 0; j < 8; j++) {
        int idx = fl * 8 + j;
        xa[j] = (idx < 61) ? xr[idx] : 0.0f;
    }
    unsigned long long o0 = 0ULL, o1 = 0ULL;
#pragma unroll
    for (int k = 0; k < 61; k++) {
        float a = __shfl_sync(0xffffffffu, xa[k & 7], (g << 3) | (k >> 3));
        unsigned long long a2 = pack2(a, a);
        ulonglong2 w = Wq[k * 8 + fl];
        o0 = fma2_(a2, w.x, o0);
        o1 = fma2_(a2, w.y, o1);
    }
    if (valid) {
        float di = rsqrtf((float)g_cnt[node] + 1.0f);   // +1 self loop
        float v0, v1, v2, v3;
        unpack2(o0, v0, v1);
        unpack2(o1, v2, v3);
        __half2 h0 = __floats2half2_rn(v0 * di, v1 * di);
        __half2 h1 = __floats2half2_rn(v2 * di, v3 * di);
        uint2 pv;
        pv.x = *(unsigned*)&h0;
        pv.y = *(unsigned*)&h1;
        *(uint2*)&g_hA[node * HD + 4 * fl] = pv;
    }
}

// ---------------- agg helpers ------------------------------------------------
__device__ __forceinline__ void acc_add8(float* acc, int4 v) {
    const __half2* h = (const __half2*)&v;
#pragma unroll
    for (int q = 0; q < 4; q++) {
        float2 f = __half22float2(h[q]);
        acc[2 * q] += f.x; acc[2 * q + 1] += f.y;
    }
}
__device__ __forceinline__ void acc_add4x8(float* acc, int4 v0, int4 v1,
                                           int4 v2, int4 v3) {
    const __half2* a = (const __half2*)&v0;
    const __half2* b = (const __half2*)&v1;
    const __half2* c = (const __half2*)&v2;
    const __half2* d = (const __half2*)&v3;
#pragma unroll
    for (int q = 0; q < 4; q++) {
        __half2 s = __hadd2(__hadd2(a[q], b[q]), __hadd2(c[q], d[q]));
        float2 f = __half22float2(s);
        acc[2 * q] += f.x; acc[2 * q + 1] += f.y;
    }
}

// ---------------- fused: aggregate -> bias -> relu -> next GEMM -> *dinv ----
// EIGHT nodes per warp: group g = lane>>2, chunk c = lane&3.
// __launch_bounds__(256,5): cap regs to lift occupancy (L1/latency mixed).
template <bool IN_A>
__global__ void __launch_bounds__(256, 5)
agg_gemm_kernel(const float* __restrict__ bias,
                const float* __restrict__ Wn, int n) {
    __shared__ ulonglong2 Wq[HD * 8];
    for (int i = threadIdx.x; i < HD * 8; i += blockDim.x) {
        float4 f = ((const float4*)Wn)[i];
        ulonglong2 u;
        u.x = pack2(f.x, f.y);
        u.y = pack2(f.z, f.w);
        Wq[i] = u;
    }
    __syncthreads();
    int warp = (blockIdx.x * blockDim.x + threadIdx.x) >> 5;
    int lane = threadIdx.x & 31;
    int g    = lane >> 2;
    int c    = lane & 3;
    int gb   = g << 2;                  // group lane base
    int node = warp * 8 + g;
    if (warp * 8 >= n) return;
    bool valid = node < n;
    int nd = valid ? node : n - 1;
    const int4* __restrict__ hin4 = (const int4*)(IN_A ? g_hA : g_hB);
    int4* __restrict__ hout4      = (int4*)(IN_A ? g_hB : g_hA);
    int cnt  = g_cnt[nd];
    float di = rsqrtf((float)cnt + 1.0f);
    int deg  = valid ? min(cnt, STRIDE) : 0;
    float acc[8] = {0, 0, 0, 0, 0, 0, 0, 0};
    acc_add8(acc, hin4[nd * 4 + c]);                     // self loop
    long long s = (long long)nd * STRIDE;
    int mmax = deg;
    mmax = max(mmax, __shfl_xor_sync(0xffffffffu, mmax, 4));
    mmax = max(mmax, __shfl_xor_sync(0xffffffffu, mmax, 8));
    mmax = max(mmax, __shfl_xor_sync(0xffffffffu, mmax, 16));
    const int4 zero4 = make_int4(0, 0, 0, 0);
    int cs = (c < deg) ? g_csrc[s + c] : 0;              // prefetch i=0
    for (int i = 0; i < mmax; i += 4) {
        int csn = (i + 4 + c < deg) ? g_csrc[s + i + 4 + c] : 0;
        int s0 = __shfl_sync(0xffffffffu, cs, gb);
        int s1 = __shfl_sync(0xffffffffu, cs, gb + 1);
        int s2 = __shfl_sync(0xffffffffu, cs, gb + 2);
        int s3 = __shfl_sync(0xffffffffu, cs, gb + 3);
        int4 v0 = (i + 0 < deg) ? hin4[s0 * 4 + c] : zero4;
        int4 v1 = (i + 1 < deg) ? hin4[s1 * 4 + c] : zero4;
        int4 v2 = (i + 2 < deg) ? hin4[s2 * 4 + c] : zero4;
        int4 v3 = (i + 3 < deg) ? hin4[s3 * 4 + c] : zero4;
        acc_add4x8(acc, v0, v1, v2, v3);
        cs = csn;
    }
    float4 b0 = ((const float4*)bias)[c * 2];
    float4 b1 = ((const float4*)bias)[c * 2 + 1];
    float r[8];
    r[0] = fmaxf(fmaf(acc[0], di, b0.x), 0.0f);
    r[1] = fmaxf(fmaf(acc[1], di, b0.y), 0.0f);
    r[2] = fmaxf(fmaf(acc[2], di, b0.z), 0.0f);
    r[3] = fmaxf(fmaf(acc[3], di, b0.w), 0.0f);
    r[4] = fmaxf(fmaf(acc[4], di, b1.x), 0.0f);
    r[5] = fmaxf(fmaf(acc[5], di, b1.y), 0.0f);
    r[6] = fmaxf(fmaf(acc[6], di, b1.z), 0.0f);
    r[7] = fmaxf(fmaf(acc[7], di, b1.w), 0.0f);
    unsigned long long o2[4] = {0ULL, 0ULL, 0ULL, 0ULL};
#pragma unroll
    for (int k = 0; k < HD; k++) {
        float a = __shfl_sync(0xffffffffu, r[k & 7], gb + (k >> 3));
        unsigned long long a2 = pack2(a, a);
        ulonglong2 w0 = Wq[k * 8 + c * 2];
        ulonglong2 w1 = Wq[k * 8 + c * 2 + 1];
        o2[0] = fma2_(a2, w0.x, o2[0]);
        o2[1] = fma2_(a2, w0.y, o2[1]);
        o2[2] = fma2_(a2, w1.x, o2[2]);
        o2[3] = fma2_(a2, w1.y, o2[3]);
    }
    if (valid) {
        float v0, v1, v2, v3, v4, v5, v6, v7;
        unpack2(o2[0], v0, v1);
        unpack2(o2[1], v2, v3);
        unpack2(o2[2], v4, v5);
        unpack2(o2[3], v6, v7);
        int4 pv;
        __half2* ph = (__half2*)&pv;
        ph[0] = __floats2half2_rn(v0 * di, v1 * di);
        ph[1] = __floats2half2_rn(v2 * di, v3 * di);
        ph[2] = __floats2half2_rn(v4 * di, v5 * di);
        ph[3] = __floats2half2_rn(v6 * di, v7 * di);
        hout4[node * 4 + c] = pv;
    }
}

// ---------------- fused final: agg -> bias -> relu -> pool -> MLP head ------
template <bool IN_A>
__global__ void agg_pool_mlp_kernel(const float* __restrict__ bias, int n,
                                    const float* __restrict__ Wl1,
                                    const float* __restrict__ bl1,
                                    const float* __restrict__ Wl2,
                                    const float* __restrict__ bl2,
                                    float* __restrict__ out) {
    __shared__ float sh[32 * 32];
    __shared__ int sh_last;
    int tid  = threadIdx.x;
    int lane = tid & 31;
    int wid  = tid >> 5;
    int g    = lane >> 2;
    int c    = lane & 3;
    int gb   = g << 2;
    int warp = (blockIdx.x * 1024 + tid) >> 5;
    int node = warp * 8 + g;
    bool valid = node < n;
    int nd = valid ? node : n - 1;
    const int4* __restrict__ hin4 = (const int4*)(IN_A ? g_hA : g_hB);
    int cnt  = g_cnt[nd];
    if (valid && c == 0) g_cnt[node] = 0;                // restore for next run
    float di = rsqrtf((float)cnt + 1.0f);
    int deg  = valid ? min(cnt, STRIDE) : 0;
    float acc[8] = {0, 0, 0, 0, 0, 0, 0, 0};
    acc_add8(acc, hin4[nd * 4 + c]);                     // self loop
    long long s = (long long)nd * STRIDE;
    int mmax = deg;
    mmax = max(mmax, __shfl_xor_sync(0xffffffffu, mmax, 4));
    mmax = max(mmax, __shfl_xor_sync(0xffffffffu, mmax, 8));
    mmax = max(mmax, __shfl_xor_sync(0xffffffffu, mmax, 16));
    const int4 zero4 = make_int4(0, 0, 0, 0);
    int cs = (c < deg) ? g_csrc[s + c] : 0;
    for (int i = 0; i < mmax; i += 4) {
        int csn = (i + 4 + c < deg) ? g_csrc[s + i + 4 + c] : 0;
        int s0 = __shfl_sync(0xffffffffu, cs, gb);
        int s1 = __shfl_sync(0xffffffffu, cs, gb + 1);
        int s2 = __shfl_sync(0xffffffffu, cs, gb + 2);
        int s3 = __shfl_sync(0xffffffffu, cs, gb + 3);
        int4 v0 = (i + 0 < deg) ? hin4[s0 * 4 + c] : zero4;
        int4 v1 = (i + 1 < deg) ? hin4[s1 * 4 + c] : zero4;
        int4 v2 = (i + 2 < deg) ? hin4[s2 * 4 + c] : zero4;
        int4 v3 = (i + 3 < deg) ? hin4[s3 * 4 + c] : zero4;
        acc_add4x8(acc, v0, v1, v2, v3);
        cs = csn;
    }
    float4 b0 = ((const float4*)bias)[c * 2];
    float4 b1 = ((const float4*)bias)[c * 2 + 1];
    float r[8];
    r[0] = fmaxf(fmaf(acc[0], di, b0.x), 0.0f);
    r[1] = fmaxf(fmaf(acc[1], di, b0.y), 0.0f);
    r[2] = fmaxf(fmaf(acc[2], di, b0.z), 0.0f);
    r[3] = fmaxf(fmaf(acc[3], di, b0.w), 0.0f);
    r[4] = fmaxf(fmaf(acc[4], di, b1.x), 0.0f);
    r[5] = fmaxf(fmaf(acc[5], di, b1.y), 0.0f);
    r[6] = fmaxf(fmaf(acc[6], di, b1.z), 0.0f);
    r[7] = fmaxf(fmaf(acc[7], di, b1.w), 0.0f);
    if (!valid) {
#pragma unroll
        for (int kk = 0; kk < 8; kk++) r[kk] = 0.0f;
    }
#pragma unroll
    for (int kk = 0; kk < 8; kk++) {
        r[kk] += __shfl_xor_sync(0xffffffffu, r[kk], 4);
        r[kk] += __shfl_xor_sync(0xffffffffu, r[kk], 8);
        r[kk] += __shfl_xor_sync(0xffffffffu, r[kk], 16);
    }
    if (lane < 4) {
#pragma unroll
        for (int kk = 0; kk < 8; kk++)
            sh[wid * 32 + c * 8 + kk] = r[kk];
    }
    __syncthreads();
    if (wid == 0) {
        float s2 = 0.0f;
#pragma unroll
        for (int j = 0; j < 32; j++) s2 += sh[j * 32 + lane];
        atomicAdd(&g_pool[lane], s2);
        __threadfence();
    }
    __syncthreads();
    if (tid == 0) {
        int t = atomicAdd(&g_done, 1);
        sh_last = (t == (int)gridDim.x - 1);
    }
    __syncthreads();
    if (sh_last && wid == 0) {
        float pv = atomicAdd(&g_pool[lane], 0.0f);
        sh[lane] = pv;
        g_pool[lane] = 0.0f;                     // restore for next run
        if (lane == 0) g_done = 0;
        __syncwarp();
        if (lane < 16) {
            float sacc = bl1[lane];
#pragma unroll
            for (int k = 0; k < 32; k++)
                sacc = fmaf(sh[k], Wl1[k * 16 + lane], sacc);
            sh[32 + lane] = fmaxf(sacc, 0.0f);
        }
        __syncwarp();
        if (lane < 3) {
            float sacc = bl2[lane];
#pragma unroll
            for (int j = 0; j < 16; j++)
                sacc = fmaf(sh[32 + j], Wl2[j * 3 + lane], sacc);
            out[lane] = sacc;
        }
    }
}

// ---------------- launch -----------------------------------------------------
extern "C" void kernel_launch(void* const* d_in, const int* in_sizes, int n_in,
                              void* d_out, int out_size) {
    const float* x   = (const float*)d_in[0];
    const int*   ei  = (const int*)d_in[1];   // int32 (JAX x64 disabled)
    const float* W1  = (const float*)d_in[2];
    const float* b1  = (const float*)d_in[3];
    const float* W2  = (const float*)d_in[4];
    const float* b2  = (const float*)d_in[5];
    const float* W3  = (const float*)d_in[6];
    const float* b3  = (const float*)d_in[7];
    const float* W4  = (const float*)d_in[8];
    const float* b4  = (const float*)d_in[9];
    const float* Wl1 = (const float*)d_in[10];
    const float* bl1 = (const float*)d_in[11];
    const float* Wl2 = (const float*)d_in[12];
    const float* bl2 = (const float*)d_in[13];
    float*       out = (float*)d_out;

    const int fin = in_sizes[2] / HD;       // 61
    const int n   = in_sizes[0] / fin;      // 150000
    const int e   = in_sizes[1] / 2;        // 2400000

    const int T = 256;
    int eB = ((e + 1) / 2 + T - 1) / T;                   // 2 edges/thread
    int nwarps4 = (n + 3) / 4;                            // gemm1: 4 nodes/warp
    int gB = (int)(((long long)nwarps4 * 32 + T - 1) / T);
    int nwarps8 = (n + 7) / 8;                            // agg: 8 nodes/warp
    int aB = (int)(((long long)nwarps8 * 32 + T - 1) / T);
    int pB = (int)(((long long)nwarps8 * 32 + 1023) / 1024);

    // --- graph structure: single bucket-scatter pass ---
    scatter_kernel<<<eB, T>>>(ei, e, n);

    // --- layers (fused agg+gemm; ping-pong A/B) ---
    gemm1_kernel<<<gB, T>>>(x, W1, n);                 // x@W1*dinv -> A
    agg_gemm_kernel<true ><<<aB, T>>>(b1, W2, n);      // agg(A)->B
    agg_gemm_kernel<false><<<aB, T>>>(b2, W3, n);      // agg(B)->A
    agg_gemm_kernel<true ><<<aB, T>>>(b3, W4, n);      // agg(A)->B
    agg_pool_mlp_kernel<false><<<pB, 1024>>>(b4, n, Wl1, bl1, Wl2, bl2, out);
}

// round 14
// speedup vs baseline: 1.0513x; 1.0513x over previous
#include <cuda_runtime.h>
#include <cuda_fp16.h>

// Problem constants (fixed by the dataset)
constexpr int NMAX   = 150000;
constexpr int HD     = 32;   // hidden dim
constexpr int STRIDE = 64;   // bucket capacity per node (P(deg>64) ~ 1e-14)

// ---------------- scratch (device globals; zero-init at load) ---------------
// Self-restoring: g_cnt reset by pool kernel, g_pool/g_done by its last block.
__device__ __half g_hA[(long long)NMAX * HD];    // ping features (h*dinv, fp16)
__device__ __half g_hB[(long long)NMAX * HD];    // pong features
__device__ int    g_cnt[NMAX];                   // bucket fill counts == degree
__device__ int    g_csrc[(long long)NMAX * STRIDE]; // bucketed src ids
__device__ float  g_pool[HD];                    // sum-pool result
__device__ int    g_done;                        // pool completion ticket

// ---------------- f32x2 packed math helpers ---------------------------------
__device__ __forceinline__ unsigned long long pack2(float x, float y) {
    unsigned long long r;
    asm("mov.b64 %0, {%1, %2};" : "=l"(r) : "f"(x), "f"(y));
    return r;
}
__device__ __forceinline__ void unpack2(unsigned long long v, float& x, float& y) {
    asm("mov.b64 {%0, %1}, %2;" : "=f"(x), "=f"(y) : "l"(v));
}
__device__ __forceinline__ unsigned long long fma2_(unsigned long long a,
                                                    unsigned long long b,
                                                    unsigned long long c) {
    unsigned long long d;
    asm("fma.rn.f32x2 %0, %1, %2, %3;" : "=l"(d) : "l"(a), "l"(b), "l"(c));
    return d;
}

// ---------------- bucket scatter (2 edges per thread) ------------------------
// edge_index is int32: ei[0:E]=src, ei[E:2E]=dst
__global__ void scatter_kernel(const int* __restrict__ ei, int E, int n) {
    int t = blockIdx.x * blockDim.x + threadIdx.x;
#pragma unroll
    for (int j = 0; j < 2; j++) {
        int e = t * 2 + j;
        if (e >= E) return;
        unsigned s = (unsigned)ei[e];
        unsigned d = (unsigned)ei[E + e];
        if (s < (unsigned)n && d < (unsigned)n) {
            int pos = atomicAdd(&g_cnt[d], 1);
            if (pos < STRIDE) g_csrc[(long long)d * STRIDE + pos] = (int)s;
        }
    }
}

// ---------------- layer 1: g_hA = (x @ W1) * dinv, fp16 out -----------------
// FOUR nodes per warp: g = lane>>3, fl = lane&7; lane owns 4 outputs (2 f32x2).
__global__ void gemm1_kernel(const float* __restrict__ x,
                             const float* __restrict__ W, int n) {
    __shared__ ulonglong2 Wq[61 * 8];   // Wq[k*8+q] = W[k][4q..4q+3] as 2xf32x2
    for (int i = threadIdx.x; i < 61 * 8; i += blockDim.x) {
        float4 f = ((const float4*)W)[i];
        ulonglong2 u;
        u.x = pack2(f.x, f.y);
        u.y = pack2(f.z, f.w);
        Wq[i] = u;
    }
    __syncthreads();
    int warp = (blockIdx.x * blockDim.x + threadIdx.x) >> 5;
    int lane = threadIdx.x & 31;
    int g    = lane >> 3;
    int fl   = lane & 7;
    int node = warp * 4 + g;
    if (warp * 4 >= n) return;
    bool valid = node < n;
    int nd = valid ? node : n - 1;
    const float* xr = x + (long long)nd * 61;
    float xa[8];
#pragma unroll
    for (int j = 0; j < 8; j++) {
        int idx = fl * 8 + j;
        xa[j] = (idx < 61) ? xr[idx] : 0.0f;
    }
    unsigned long long o0 = 0ULL, o1 = 0ULL;
#pragma unroll
    for (int k = 0; k < 61; k++) {
        float a = __shfl_sync(0xffffffffu, xa[k & 7], (g << 3) | (k >> 3));
        unsigned long long a2 = pack2(a, a);
        ulonglong2 w = Wq[k * 8 + fl];
        o0 = fma2_(a2, w.x, o0);
        o1 = fma2_(a2, w.y, o1);
    }
    if (valid) {
        float di = rsqrtf((float)g_cnt[node] + 1.0f);   // +1 self loop
        float v0, v1, v2, v3;
        unpack2(o0, v0, v1);
        unpack2(o1, v2, v3);
        __half2 h0 = __floats2half2_rn(v0 * di, v1 * di);
        __half2 h1 = __floats2half2_rn(v2 * di, v3 * di);
        uint2 pv;
        pv.x = *(unsigned*)&h0;
        pv.y = *(unsigned*)&h1;
        *(uint2*)&g_hA[node * HD + 4 * fl] = pv;
    }
}

// ---------------- agg helpers ------------------------------------------------
__device__ __forceinline__ void acc_add8(float* acc, int4 v) {
    const __half2* h = (const __half2*)&v;
#pragma unroll
    for (int q = 0; q < 4; q++) {
        float2 f = __half22float2(h[q]);
        acc[2 * q] += f.x; acc[2 * q + 1] += f.y;
    }
}
__device__ __forceinline__ void acc_add4x8(float* acc, int4 v0, int4 v1,
                                           int4 v2, int4 v3) {
    const __half2* a = (const __half2*)&v0;
    const __half2* b = (const __half2*)&v1;
    const __half2* c = (const __half2*)&v2;
    const __half2* d = (const __half2*)&v3;
#pragma unroll
    for (int q = 0; q < 4; q++) {
        __half2 s = __hadd2(__hadd2(a[q], b[q]), __hadd2(c[q], d[q]));
        float2 f = __half22float2(s);
        acc[2 * q] += f.x; acc[2 * q + 1] += f.y;
    }
}

// Shared 8-edge-unrolled aggregation body: fills acc[8] for this lane's chunk.
// g = node group (lane>>2), c = chunk (lane&3), gb = g<<2.
template <bool IN_A>
__device__ __forceinline__ void agg_body(float* acc, int nd, int deg, int mmax,
                                         int c, int gb) {
    const int4* __restrict__ hin4 = (const int4*)(IN_A ? g_hA : g_hB);
    acc_add8(acc, hin4[nd * 4 + c]);                     // self loop
    long long s = (long long)nd * STRIDE;
    const int4 zero4 = make_int4(0, 0, 0, 0);
    int cs0 = (c < deg)     ? g_csrc[s + c]     : 0;     // prefetch edges 0..3
    int cs1 = (4 + c < deg) ? g_csrc[s + 4 + c] : 0;     // prefetch edges 4..7
    for (int i = 0; i < mmax; i += 8) {
        int n0 = (i + 8 + c < deg)  ? g_csrc[s + i + 8 + c]  : 0;
        int n1 = (i + 12 + c < deg) ? g_csrc[s + i + 12 + c] : 0;
        int s0 = __shfl_sync(0xffffffffu, cs0, gb);
        int s1 = __shfl_sync(0xffffffffu, cs0, gb + 1);
        int s2 = __shfl_sync(0xffffffffu, cs0, gb + 2);
        int s3 = __shfl_sync(0xffffffffu, cs0, gb + 3);
        int s4 = __shfl_sync(0xffffffffu, cs1, gb);
        int s5 = __shfl_sync(0xffffffffu, cs1, gb + 1);
        int s6 = __shfl_sync(0xffffffffu, cs1, gb + 2);
        int s7 = __shfl_sync(0xffffffffu, cs1, gb + 3);
        int4 v0 = (i + 0 < deg) ? hin4[s0 * 4 + c] : zero4;
        int4 v1 = (i + 1 < deg) ? hin4[s1 * 4 + c] : zero4;
        int4 v2 = (i + 2 < deg) ? hin4[s2 * 4 + c] : zero4;
        int4 v3 = (i + 3 < deg) ? hin4[s3 * 4 + c] : zero4;
        int4 v4 = (i + 4 < deg) ? hin4[s4 * 4 + c] : zero4;
        int4 v5 = (i + 5 < deg) ? hin4[s5 * 4 + c] : zero4;
        int4 v6 = (i + 6 < deg) ? hin4[s6 * 4 + c] : zero4;
        int4 v7 = (i + 7 < deg) ? hin4[s7 * 4 + c] : zero4;
        acc_add4x8(acc, v0, v1, v2, v3);
        acc_add4x8(acc, v4, v5, v6, v7);
        cs0 = n0;
        cs1 = n1;
    }
}

// ---------------- fused: aggregate -> bias -> relu -> next GEMM -> *dinv ----
// EIGHT nodes per warp: group g = lane>>2, chunk c = lane&3.
template <bool IN_A>
__global__ void agg_gemm_kernel(const float* __restrict__ bias,
                                const float* __restrict__ Wn, int n) {
    __shared__ ulonglong2 Wq[HD * 8];
    for (int i = threadIdx.x; i < HD * 8; i += blockDim.x) {
        float4 f = ((const float4*)Wn)[i];
        ulonglong2 u;
        u.x = pack2(f.x, f.y);
        u.y = pack2(f.z, f.w);
        Wq[i] = u;
    }
    __syncthreads();
    int warp = (blockIdx.x * blockDim.x + threadIdx.x) >> 5;
    int lane = threadIdx.x & 31;
    int g    = lane >> 2;
    int c    = lane & 3;
    int gb   = g << 2;
    int node = warp * 8 + g;
    if (warp * 8 >= n) return;
    bool valid = node < n;
    int nd = valid ? node : n - 1;
    int4* __restrict__ hout4 = (int4*)(IN_A ? g_hB : g_hA);
    int cnt  = g_cnt[nd];
    float di = rsqrtf((float)cnt + 1.0f);
    int deg  = valid ? min(cnt, STRIDE) : 0;
    int mmax = deg;
    mmax = max(mmax, __shfl_xor_sync(0xffffffffu, mmax, 4));
    mmax = max(mmax, __shfl_xor_sync(0xffffffffu, mmax, 8));
    mmax = max(mmax, __shfl_xor_sync(0xffffffffu, mmax, 16));
    float acc[8] = {0, 0, 0, 0, 0, 0, 0, 0};
    agg_body<IN_A>(acc, nd, deg, mmax, c, gb);
    float4 b0 = ((const float4*)bias)[c * 2];
    float4 b1 = ((const float4*)bias)[c * 2 + 1];
    float r[8];
    r[0] = fmaxf(fmaf(acc[0], di, b0.x), 0.0f);
    r[1] = fmaxf(fmaf(acc[1], di, b0.y), 0.0f);
    r[2] = fmaxf(fmaf(acc[2], di, b0.z), 0.0f);
    r[3] = fmaxf(fmaf(acc[3], di, b0.w), 0.0f);
    r[4] = fmaxf(fmaf(acc[4], di, b1.x), 0.0f);
    r[5] = fmaxf(fmaf(acc[5], di, b1.y), 0.0f);
    r[6] = fmaxf(fmaf(acc[6], di, b1.z), 0.0f);
    r[7] = fmaxf(fmaf(acc[7], di, b1.w), 0.0f);
    unsigned long long o2[4] = {0ULL, 0ULL, 0ULL, 0ULL};
#pragma unroll
    for (int k = 0; k < HD; k++) {
        float a = __shfl_sync(0xffffffffu, r[k & 7], gb + (k >> 3));
        unsigned long long a2 = pack2(a, a);
        ulonglong2 w0 = Wq[k * 8 + c * 2];
        ulonglong2 w1 = Wq[k * 8 + c * 2 + 1];
        o2[0] = fma2_(a2, w0.x, o2[0]);
        o2[1] = fma2_(a2, w0.y, o2[1]);
        o2[2] = fma2_(a2, w1.x, o2[2]);
        o2[3] = fma2_(a2, w1.y, o2[3]);
    }
    if (valid) {
        float v0, v1, v2, v3, v4, v5, v6, v7;
        unpack2(o2[0], v0, v1);
        unpack2(o2[1], v2, v3);
        unpack2(o2[2], v4, v5);
        unpack2(o2[3], v6, v7);
        int4 pv;
        __half2* ph = (__half2*)&pv;
        ph[0] = __floats2half2_rn(v0 * di, v1 * di);
        ph[1] = __floats2half2_rn(v2 * di, v3 * di);
        ph[2] = __floats2half2_rn(v4 * di, v5 * di);
        ph[3] = __floats2half2_rn(v6 * di, v7 * di);
        hout4[node * 4 + c] = pv;
    }
}

// ---------------- fused final: agg -> bias -> relu -> pool -> MLP head ------
template <bool IN_A>
__global__ void agg_pool_mlp_kernel(const float* __restrict__ bias, int n,
                                    const float* __restrict__ Wl1,
                                    const float* __restrict__ bl1,
                                    const float* __restrict__ Wl2,
                                    const float* __restrict__ bl2,
                                    float* __restrict__ out) {
    __shared__ float sh[32 * 32];
    __shared__ int sh_last;
    int tid  = threadIdx.x;
    int lane = tid & 31;
    int wid  = tid >> 5;
    int g    = lane >> 2;
    int c    = lane & 3;
    int gb   = g << 2;
    int warp = (blockIdx.x * 1024 + tid) >> 5;
    int node = warp * 8 + g;
    bool valid = node < n;
    int nd = valid ? node : n - 1;
    int cnt  = g_cnt[nd];
    if (valid && c == 0) g_cnt[node] = 0;                // restore for next run
    float di = rsqrtf((float)cnt + 1.0f);
    int deg  = valid ? min(cnt, STRIDE) : 0;
    int mmax = deg;
    mmax = max(mmax, __shfl_xor_sync(0xffffffffu, mmax, 4));
    mmax = max(mmax, __shfl_xor_sync(0xffffffffu, mmax, 8));
    mmax = max(mmax, __shfl_xor_sync(0xffffffffu, mmax, 16));
    float acc[8] = {0, 0, 0, 0, 0, 0, 0, 0};
    agg_body<IN_A>(acc, nd, deg, mmax, c, gb);
    float4 b0 = ((const float4*)bias)[c * 2];
    float4 b1 = ((const float4*)bias)[c * 2 + 1];
    float r[8];
    r[0] = fmaxf(fmaf(acc[0], di, b0.x), 0.0f);
    r[1] = fmaxf(fmaf(acc[1], di, b0.y), 0.0f);
    r[2] = fmaxf(fmaf(acc[2], di, b0.z), 0.0f);
    r[3] = fmaxf(fmaf(acc[3], di, b0.w), 0.0f);
    r[4] = fmaxf(fmaf(acc[4], di, b1.x), 0.0f);
    r[5] = fmaxf(fmaf(acc[5], di, b1.y), 0.0f);
    r[6] = fmaxf(fmaf(acc[6], di, b1.z), 0.0f);
    r[7] = fmaxf(fmaf(acc[7], di, b1.w), 0.0f);
    if (!valid) {
#pragma unroll
        for (int kk = 0; kk < 8; kk++) r[kk] = 0.0f;
    }
#pragma unroll
    for (int kk = 0; kk < 8; kk++) {
        r[kk] += __shfl_xor_sync(0xffffffffu, r[kk], 4);
        r[kk] += __shfl_xor_sync(0xffffffffu, r[kk], 8);
        r[kk] += __shfl_xor_sync(0xffffffffu, r[kk], 16);
    }
    if (lane < 4) {
#pragma unroll
        for (int kk = 0; kk < 8; kk++)
            sh[wid * 32 + c * 8 + kk] = r[kk];
    }
    __syncthreads();
    if (wid == 0) {
        float s2 = 0.0f;
#pragma unroll
        for (int j = 0; j < 32; j++) s2 += sh[j * 32 + lane];
        atomicAdd(&g_pool[lane], s2);
        __threadfence();
    }
    __syncthreads();
    if (tid == 0) {
        int t = atomicAdd(&g_done, 1);
        sh_last = (t == (int)gridDim.x - 1);
    }
    __syncthreads();
    if (sh_last && wid == 0) {
        float pv = atomicAdd(&g_pool[lane], 0.0f);
        sh[lane] = pv;
        g_pool[lane] = 0.0f;                     // restore for next run
        if (lane == 0) g_done = 0;
        __syncwarp();
        if (lane < 16) {
            float sacc = bl1[lane];
#pragma unroll
            for (int k = 0; k < 32; k++)
                sacc = fmaf(sh[k], Wl1[k * 16 + lane], sacc);
            sh[32 + lane] = fmaxf(sacc, 0.0f);
        }
        __syncwarp();
        if (lane < 3) {
            float sacc = bl2[lane];
#pragma unroll
            for (int j = 0; j < 16; j++)
                sacc = fmaf(sh[32 + j], Wl2[j * 3 + lane], sacc);
            out[lane] = sacc;
        }
    }
}

// ---------------- launch -----------------------------------------------------
extern "C" void kernel_launch(void* const* d_in, const int* in_sizes, int n_in,
                              void* d_out, int out_size) {
    const float* x   = (const float*)d_in[0];
    const int*   ei  = (const int*)d_in[1];   // int32 (JAX x64 disabled)
    const float* W1  = (const float*)d_in[2];
    const float* b1  = (const float*)d_in[3];
    const float* W2  = (const float*)d_in[4];
    const float* b2  = (const float*)d_in[5];
    const float* W3  = (const float*)d_in[6];
    const float* b3  = (const float*)d_in[7];
    const float* W4  = (const float*)d_in[8];
    const float* b4  = (const float*)d_in[9];
    const float* Wl1 = (const float*)d_in[10];
    const float* bl1 = (const float*)d_in[11];
    const float* Wl2 = (const float*)d_in[12];
    const float* bl2 = (const float*)d_in[13];
    float*       out = (float*)d_out;

    const int fin = in_sizes[2] / HD;       // 61
    const int n   = in_sizes[0] / fin;      // 150000
    const int e   = in_sizes[1] / 2;        // 2400000

    const int T = 256;
    int eB = ((e + 1) / 2 + T - 1) / T;                   // 2 edges/thread
    int nwarps4 = (n + 3) / 4;                            // gemm1: 4 nodes/warp
    int gB = (int)(((long long)nwarps4 * 32 + T - 1) / T);
    int nwarps8 = (n + 7) / 8;                            // agg: 8 nodes/warp
    int aB = (int)(((long long)nwarps8 * 32 + T - 1) / T);
    int pB = (int)(((long long)nwarps8 * 32 + 1023) / 1024);

    // --- graph structure: single bucket-scatter pass ---
    scatter_kernel<<<eB, T>>>(ei, e, n);

    // --- layers (fused agg+gemm; ping-pong A/B) ---
    gemm1_kernel<<<gB, T>>>(x, W1, n);                 // x@W1*dinv -> A
    agg_gemm_kernel<true ><<<aB, T>>>(b1, W2, n);      // agg(A)->B
    agg_gemm_kernel<false><<<aB, T>>>(b2, W3, n);      // agg(B)->A
    agg_gemm_kernel<true ><<<aB, T>>>(b3, W4, n);      // agg(A)->B
    agg_pool_mlp_kernel<false><<<pB, 1024>>>(b4, n, Wl1, bl1, Wl2, bl2, out);
}